// round 11
// baseline (speedup 1.0000x reference)
#include <cuda_runtime.h>
#include <cuda_bf16.h>
#include <cstdint>

#define NX    512
#define NU    128
#define ND    64
#define BATCH 256
#define TT    256
#define NCTA  128

typedef unsigned long long ull;

// ---------------- device scratch (allocation-free) ----------------
__device__ float    g_R [NX * NX];      // R[k][j] = W_eff[j][k]
__device__ float    g_W [NX * NX];      // W_eff row-major: g_W[j][k] = R[k][j]
__device__ float    g_R2[NX * NX];      // (W^2)^T: R2 = R·R
__device__ float    g_Bp[NX * NU];      // Bp = R·Bw   (so inj·W uses U·Bp^T)
__device__ float    g_Ep[NX * ND];      // Ep = R·Ew
__device__ unsigned g_cnt[16 * 32];     // per-batch-group monotonic counters

// ---------------- helpers ----------------
__device__ __forceinline__ void ffma2(ull& acc, ull a, ull b) {
    asm volatile("fma.rn.f32x2 %0, %1, %2, %0;" : "+l"(acc) : "l"(a), "l"(b));
}
__device__ __forceinline__ float hsum2(ull v) {
    float lo, hi;
    asm("mov.b64 {%0, %1}, %2;" : "=f"(lo), "=f"(hi) : "l"(v));
    return lo + hi;
}
__device__ __forceinline__ float ld_cg_f32(const float* p) {
    float v; asm volatile("ld.global.cg.f32 %0, [%1];" : "=f"(v) : "l"(p)); return v;
}
__device__ __forceinline__ void st_cg_f32(float* p, float v) {
    asm volatile("st.global.cg.f32 [%0], %1;" :: "l"(p), "f"(v));
}
__device__ __forceinline__ float4 ld_cg_f4(const float* p) {
    float4 v;
    asm volatile("ld.global.cg.v4.f32 {%0,%1,%2,%3}, [%4];"
                 : "=f"(v.x), "=f"(v.y), "=f"(v.z), "=f"(v.w) : "l"(p));
    return v;
}

// ---------------- kernel 1: W_eff prep (R and R^T) + counter reset ----------------
__global__ void __launch_bounds__(256) prep_kernel(const float* __restrict__ Aw,
                                                   const float* __restrict__ As) {
    int k = blockIdx.x;
    int tid = threadIdx.x;
    if (k == 0 && tid < 16) g_cnt[tid * 32] = 0;
    __shared__ float red[256];
    const float* row = Aw + (size_t)k * NX;
    float a0 = row[tid], a1 = row[tid + 256];
    red[tid] = fmaxf(a0, a1);
    __syncthreads();
    for (int s = 128; s > 0; s >>= 1) {
        if (tid < s) red[tid] = fmaxf(red[tid], red[tid + s]);
        __syncthreads();
    }
    float mx = red[0];
    __syncthreads();
    float e0 = expf(a0 - mx), e1 = expf(a1 - mx);
    red[tid] = e0 + e1;
    __syncthreads();
    for (int s = 128; s > 0; s >>= 1) {
        if (tid < s) red[tid] += red[tid + s];
        __syncthreads();
    }
    float inv = 1.0f / red[0];
    const float* srow = As + (size_t)k * NX;
    float z0 = srow[tid], z1 = srow[tid + 256];
    float s0 = 1.0f - 0.1f / (1.0f + expf(-z0));
    float s1 = 1.0f - 0.1f / (1.0f + expf(-z1));
    float v0 = s0 * e0 * inv, v1 = s1 * e1 * inv;
    g_R[(size_t)k * NX + tid]         = v0;     // R[k][j]
    g_R[(size_t)k * NX + tid + 256]   = v1;
    g_W[(size_t)tid * NX + k]         = v0;     // g_W[j][k] = R[k][j]
    g_W[(size_t)(tid + 256) * NX + k] = v1;
}

// ---------------- generic 64x64-tile GEMM: C[m][n] (+)= sum_k A[m][k]*Bsel[n][k] ----
// TRB=false: Bsel[n][k] = B[n*ldb+k];  TRB=true: Bsel[n][k] = B[k*ldb+n]
template <bool TRB, bool ACCUM>
__global__ void __launch_bounds__(256) gemm64_kernel(
    const float* __restrict__ A, int lda,
    const float* __restrict__ B, int ldb,
    float* __restrict__ C, int ldc, int K)
{
    __shared__ float A_s[64 * 68];
    __shared__ float W_s[64 * 68];
    int tid = threadIdx.x;
    int n0 = blockIdx.x * 64, m0 = blockIdx.y * 64;
    int tn = tid & 15, tm = tid >> 4;
    ull acc[16];
#pragma unroll
    for (int i = 0; i < 16; i++) acc[i] = 0ull;

    for (int k0 = 0; k0 < K; k0 += 64) {
        __syncthreads();
        for (int i = tid; i < 1024; i += 256) {
            int r = i >> 4, c = i & 15;
            *(float4*)(A_s + r * 68 + c * 4) =
                *(const float4*)(A + (size_t)(m0 + r) * lda + k0 + c * 4);
        }
        if (!TRB) {
            for (int i = tid; i < 1024; i += 256) {
                int r = i >> 4, c = i & 15;
                *(float4*)(W_s + r * 68 + c * 4) =
                    *(const float4*)(B + (size_t)(n0 + r) * ldb + k0 + c * 4);
            }
        } else {
            for (int i = tid; i < 4096; i += 256) {
                int k = i >> 6, n = i & 63;
                W_s[n * 68 + k] = B[(size_t)(k0 + k) * ldb + n0 + n];
            }
        }
        __syncthreads();
#pragma unroll
        for (int kp = 0; kp < 32; kp++) {
            ull a[4], w[4];
#pragma unroll
            for (int i = 0; i < 4; i++) a[i] = *(const ull*)(A_s + (tm * 4 + i) * 68 + 2 * kp);
#pragma unroll
            for (int j = 0; j < 4; j++) w[j] = *(const ull*)(W_s + (tn + 16 * j) * 68 + 2 * kp);
#pragma unroll
            for (int i = 0; i < 4; i++)
#pragma unroll
                for (int j = 0; j < 4; j++)
                    ffma2(acc[i * 4 + j], a[i], w[j]);
        }
    }
#pragma unroll
    for (int i = 0; i < 4; i++)
#pragma unroll
        for (int j = 0; j < 4; j++) {
            float v = hsum2(acc[i * 4 + j]);
            float* p = C + (size_t)(m0 + tm * 4 + i) * ldc + n0 + tn + 16 * j;
            if (ACCUM) v += *p;
            *p = v;
        }
}

// ---------------- J kernel: X[t] = U_{t-1}Bp^T + D_{t-1}Ep^T + U_t Bw^T + D_t Ew^T ----
__global__ void __launch_bounds__(256) j_kernel(
    const float* __restrict__ U, const float* __restrict__ D,
    const float* __restrict__ Bw, const float* __restrict__ Ew,
    float* __restrict__ X)
{
    __shared__ float A_s[64 * 68];
    __shared__ float W_s[64 * 68];
    int tid = threadIdx.x;
    int n0 = blockIdx.x * 64;
    int m0 = blockIdx.y * 64;
    int t = m0 >> 8, b0 = m0 & 255;
    int tn = tid & 15, tm = tid >> 4;
    ull acc[16];
#pragma unroll
    for (int i = 0; i < 16; i++) acc[i] = 0ull;

#pragma unroll 1
    for (int seg = 0; seg < 6; seg++) {
        const float* asrc; int lda; bool valid = true;
        const float* wsrc; int ldw;
        switch (seg) {
            case 0: asrc = U + ((size_t)(t - 1) * 256 + b0) * NU;      lda = NU; valid = (t > 0);
                    wsrc = g_Bp + (size_t)n0 * NU;       ldw = NU; break;
            case 1: asrc = U + ((size_t)(t - 1) * 256 + b0) * NU + 64; lda = NU; valid = (t > 0);
                    wsrc = g_Bp + (size_t)n0 * NU + 64;  ldw = NU; break;
            case 2: asrc = D + ((size_t)(t - 1) * 256 + b0) * ND;      lda = ND; valid = (t > 0);
                    wsrc = g_Ep + (size_t)n0 * ND;       ldw = ND; break;
            case 3: asrc = U + ((size_t)t * 256 + b0) * NU;            lda = NU;
                    wsrc = Bw + (size_t)n0 * NU;         ldw = NU; break;
            case 4: asrc = U + ((size_t)t * 256 + b0) * NU + 64;       lda = NU;
                    wsrc = Bw + (size_t)n0 * NU + 64;    ldw = NU; break;
            default: asrc = D + ((size_t)t * 256 + b0) * ND;           lda = ND;
                    wsrc = Ew + (size_t)n0 * ND;         ldw = ND; break;
        }
        __syncthreads();
        for (int i = tid; i < 1024; i += 256) {
            int r = i >> 4, c = i & 15;
            float4 av = valid ? *(const float4*)(asrc + (size_t)r * lda + c * 4)
                              : make_float4(0.f, 0.f, 0.f, 0.f);
            *(float4*)(A_s + r * 68 + c * 4) = av;
            *(float4*)(W_s + r * 68 + c * 4) = *(const float4*)(wsrc + (size_t)r * ldw + c * 4);
        }
        __syncthreads();
#pragma unroll
        for (int kp = 0; kp < 32; kp++) {
            ull a[4], w[4];
#pragma unroll
            for (int i = 0; i < 4; i++) a[i] = *(const ull*)(A_s + (tm * 4 + i) * 68 + 2 * kp);
#pragma unroll
            for (int j = 0; j < 4; j++) w[j] = *(const ull*)(W_s + (tn + 16 * j) * 68 + 2 * kp);
#pragma unroll
            for (int i = 0; i < 4; i++)
#pragma unroll
                for (int j = 0; j < 4; j++)
                    ffma2(acc[i * 4 + j], a[i], w[j]);
        }
    }
#pragma unroll
    for (int i = 0; i < 4; i++) {
        size_t m = m0 + tm * 4 + i;
#pragma unroll
        for (int j = 0; j < 4; j++)
            X[m * NX + n0 + tn + 16 * j] = hsum2(acc[i * 4 + j]);
    }
}

// ---------------- scan2: dual-chain W^2 persistent scan, 128 steps ----------------
#define WSTRIDE   65
#define W_BYTES   (128 * WSTRIDE * 16)          // 133120
#define BUF_B     (16 * NX * 4)                 // 32768
#define SCAN_SMEM (W_BYTES + 2 * BUF_B + 8 * 16 * 64 * 4)   // 231424

__device__ __forceinline__ void scan_tile(
    const ulonglong2* __restrict__ xb, const ulonglong2* __restrict__ Wsm,
    float* __restrict__ red, int warp, int lane)
{
    ull accA[16], accB[16];
#pragma unroll
    for (int b = 0; b < 16; b++) { accA[b] = 0ull; accB[b] = 0ull; }
    const int q0 = warp * 16;
#pragma unroll 4
    for (int q = q0; q < q0 + 16; q++) {
        ulonglong2 wa = Wsm[q * WSTRIDE + lane];
        ulonglong2 wb = Wsm[q * WSTRIDE + lane + 32];
#pragma unroll
        for (int b = 0; b < 16; b++) {
            ulonglong2 xp = xb[b * 128 + q];   // warp-broadcast
            ffma2(accA[b], xp.x, wa.x);
            ffma2(accA[b], xp.y, wa.y);
            ffma2(accB[b], xp.x, wb.x);
            ffma2(accB[b], xp.y, wb.y);
        }
    }
#pragma unroll
    for (int b = 0; b < 16; b++) {
        red[(warp * 16 + b) * 64 + lane]      = hsum2(accA[b]);
        red[(warp * 16 + b) * 64 + lane + 32] = hsum2(accB[b]);
    }
}

__device__ __forceinline__ void scan_reduce(
    const float* __restrict__ red, float* __restrict__ Xt, float* __restrict__ Y,
    int t, int tid, int gj, int gb)
{
    float inj_r[4];
#pragma unroll
    for (int r = 0; r < 4; r++) {
        int o = tid + 256 * r, b = o >> 6, kk = o & 63;
        inj_r[r] = ld_cg_f32(Xt + (size_t)b * NX + kk);
    }
#pragma unroll
    for (int r = 0; r < 4; r++) {
        int o = tid + 256 * r, b = o >> 6, kk = o & 63;
        float s = inj_r[r];
#pragma unroll
        for (int w = 0; w < 8; w++) s += red[(w * 16 + b) * 64 + kk];
        st_cg_f32(Xt + (size_t)b * NX + kk, s);
        if (gj == 7 && kk == 63)
            Y[(size_t)t * BATCH + gb * 16 + b] = s;
    }
}

__global__ void __launch_bounds__(256, 1) scan2_kernel(
    const float* __restrict__ x0, float* __restrict__ X, float* __restrict__ Y)
{
    extern __shared__ char smraw[];
    ulonglong2* Wsm   = (ulonglong2*)smraw;                 // [q*WSTRIDE + kl]
    float4*     bufA4 = (float4*)(smraw + W_BYTES);         // odd chain state
    float4*     bufB4 = (float4*)(smraw + W_BYTES + BUF_B); // even chain state
    ulonglong2* bufA2 = (ulonglong2*)bufA4;
    ulonglong2* bufB2 = (ulonglong2*)bufB4;
    float*      red   = (float*)(smraw + W_BYTES + 2 * BUF_B);

    const int tid  = threadIdx.x;
    const int lane = tid & 31;
    const int warp = tid >> 5;
    const int gj   = blockIdx.x & 7;
    const int gb   = blockIdx.x >> 3;
    unsigned* cnt  = &g_cnt[gb * 32];

    // pin W^2 slice
    for (int i = tid; i < 64 * 128; i += 256) {
        int kk = i >> 7, q = i & 127;
        float4 v = *(const float4*)(g_R2 + (size_t)(gj * 64 + kk) * NX + 4 * q);
        ((float4*)Wsm)[q * WSTRIDE + kk] = v;
    }
    // stage bufA = x0 ("X[-1]"), bufB = X[0]; extract Y[0]
    for (int i = tid; i < 2048; i += 256) {
        int b = i >> 7, c = i & 127;
        bufA4[b * 128 + c] = *(const float4*)(x0 + (size_t)(gb * 16 + b) * NX + 4 * c);
        float4 v = ld_cg_f4(X + (size_t)(gb * 16 + b) * NX + 4 * c);
        bufB4[b * 128 + c] = v;
        if (gj == 0 && c == 127) Y[gb * 16 + b] = v.w;
    }
    __syncthreads();

#pragma unroll 1
    for (int s = 0; s < 128; s++) {
        // ---- tile A: X[2s+1] = bufA * W^2 + J ----
        scan_tile(bufA2, Wsm, red, warp, lane);
        __syncthreads();
        scan_reduce(red, X + ((size_t)(2 * s + 1) * BATCH + gb * 16) * NX + gj * 64,
                    Y, 2 * s + 1, tid, gj, gb);
        if (s == 127) break;
        __syncthreads();                                    // red WAR
        // ---- tile B: X[2s+2] = bufB * W^2 + J ----
        scan_tile(bufB2, Wsm, red, warp, lane);
        __syncthreads();
        scan_reduce(red, X + ((size_t)(2 * s + 2) * BATCH + gb * 16) * NX + gj * 64,
                    Y, 2 * s + 2, tid, gj, gb);
        // ---- group barrier (R4-proven release/acquire) ----
        __threadfence();
        __syncthreads();
        if (tid == 0) {
            atomicAdd(cnt, 1u);
            unsigned target = 8u * (unsigned)(s + 1);
            while (atomicAdd(cnt, 0u) < target) { }
            __threadfence();
        }
        __syncthreads();
        // ---- stage both chains ----
        const float* srcA = X + ((size_t)(2 * s + 1) * BATCH + gb * 16) * NX;
        const float* srcB = X + ((size_t)(2 * s + 2) * BATCH + gb * 16) * NX;
        for (int i = tid; i < 2048; i += 256) {
            int b = i >> 7, c = i & 127;
            bufA4[b * 128 + c] = ld_cg_f4(srcA + (size_t)b * NX + 4 * c);
            bufB4[b * 128 + c] = ld_cg_f4(srcB + (size_t)b * NX + 4 * c);
        }
        __syncthreads();
    }
}

// ---------------- launch ----------------
extern "C" void kernel_launch(void* const* d_in, const int* in_sizes, int n_in,
                              void* d_out, int out_size) {
    const float* x0 = (const float*)d_in[0];
    const float* U  = (const float*)d_in[1];
    const float* D  = (const float*)d_in[2];
    const float* Aw = (const float*)d_in[3];
    const float* As = (const float*)d_in[4];
    const float* Bw = (const float*)d_in[5];
    const float* Ew = (const float*)d_in[6];
    float* X = (float*)d_out;                   // [T][BATCH][NX]
    float* Y = X + (size_t)TT * BATCH * NX;     // [T][BATCH]

    float* pR  = nullptr; cudaGetSymbolAddress((void**)&pR,  g_R);
    float* pW  = nullptr; cudaGetSymbolAddress((void**)&pW,  g_W);
    float* pR2 = nullptr; cudaGetSymbolAddress((void**)&pR2, g_R2);
    float* pBp = nullptr; cudaGetSymbolAddress((void**)&pBp, g_Bp);
    float* pEp = nullptr; cudaGetSymbolAddress((void**)&pEp, g_Ep);

    cudaFuncSetAttribute(scan2_kernel, cudaFuncAttributeMaxDynamicSharedMemorySize, SCAN_SMEM);

    prep_kernel<<<NX, 256>>>(Aw, As);
    // R2 = R * R   (C[k][j] = sum_m R[k][m] * g_W[j][m], g_W[j][m] = R[m][j])
    gemm64_kernel<false, false><<<dim3(8, 8), 256>>>(pR, NX, pW, NX, pR2, NX, NX);
    // Bp = R * Bw, Ep = R * Ew
    gemm64_kernel<true, false><<<dim3(2, 8), 256>>>(pR, NX, Bw, NU, pBp, NU, NX);
    gemm64_kernel<true, false><<<dim3(1, 8), 256>>>(pR, NX, Ew, ND, pEp, ND, NX);
    // J_t -> X[t]  (t=0 reduces to inj_0)
    j_kernel<<<dim3(8, (TT * BATCH) / 64), 256>>>(U, D, Bw, Ew, X);
    // X[0] += x0 * W_eff  (seed of even chain)
    gemm64_kernel<false, true><<<dim3(8, 4), 256>>>(x0, NX, pR, NX, X, NX, NX);
    // dual-chain scan, 128 steps
    scan2_kernel<<<NCTA, 256, SCAN_SMEM>>>(x0, X, Y);
}